// round 5
// baseline (speedup 1.0000x reference)
#include <cuda_runtime.h>
#include <cstdint>

// ---------------------------------------------------------------------------
// Problem constants
// ---------------------------------------------------------------------------
#define BS       8
#define CCH      32
#define TLEN     2048
#define PATCH_N  16
#define DM       512
#define NHEADS   8
#define HD       64
#define DFF      2048
#define NLAYERS  3
#define BSEQ     (BS * CCH)       // 256
#define LTOT     240              // 16+32+64+128
#define MROWS    (BSEQ * LTOT)    // 61440

// ---------------------------------------------------------------------------
// Scratch (device globals; no allocation allowed in kernel_launch)
// ---------------------------------------------------------------------------
__device__ float g_h [MROWS * DM];
__device__ float g_q [MROWS * DM];
__device__ float g_k [MROWS * DM];
__device__ float g_v [MROWS * DM];
__device__ float g_t [MROWS * DM];
__device__ float g_ff[MROWS * DFF];

// ---------------------------------------------------------------------------
// Embedding + positional encoding
// h[row, tok, :] = sum_p x_enc[b, k*(j*16+p), cc] * W_emb[p, :] + pe[j*k, :]
// ---------------------------------------------------------------------------
__global__ void embed_kernel(const float* __restrict__ x_enc,
                             const float* __restrict__ Wemb,
                             float* __restrict__ h)
{
    int tok = blockIdx.x;       // 0..239
    int r   = blockIdx.y;       // 0..255
    int tid = threadIdx.x;      // 256 threads
    int b  = r >> 5;
    int cc = r & 31;

    int kstr, j;
    if (tok < 16)       { kstr = 8; j = tok; }
    else if (tok < 48)  { kstr = 4; j = tok - 16; }
    else if (tok < 112) { kstr = 2; j = tok - 48; }
    else                { kstr = 1; j = tok - 112; }

    __shared__ float xv[PATCH_N];
    if (tid < PATCH_N) {
        int tt = kstr * (j * PATCH_N + tid);
        xv[tid] = x_enc[((size_t)b * TLEN + tt) * CCH + cc];
    }
    __syncthreads();

    float pepos = (float)(j * kstr);
    const float cln = 9.210340371976184f / (float)DM;  // ln(10000)/512

    for (int d = tid; d < DM; d += 256) {
        float acc = 0.0f;
        #pragma unroll
        for (int p = 0; p < PATCH_N; p++)
            acc += xv[p] * Wemb[p * DM + d];
        int i2 = d & ~1;
        float ang = pepos * __expf(-(float)i2 * cln);
        float pv = (d & 1) ? cosf(ang) : sinf(ang);
        h[((size_t)r * LTOT + tok) * DM + d] = acc + pv;
    }
}

// ---------------------------------------------------------------------------
// SGEMM: C[M,N] = A[M,K] @ B[K,N] + bias[N]  (+ optional tanh-GELU)
// 128x128 block tile, BK=16, 256 threads, 8x8 per thread, reg prefetch.
// M % 128 == 0, N % 128 == 0, K % 16 == 0 guaranteed by problem shapes.
// ---------------------------------------------------------------------------
#define BM 128
#define BN 128
#define BKD 16

__device__ __forceinline__ float gelu_tanh(float x) {
    float x3 = x * x * x;
    float t = tanhf(0.7978845608028654f * (x + 0.044715f * x3));
    return 0.5f * x * (1.0f + t);
}

__global__ __launch_bounds__(256, 2)
void sgemm_kernel(const float* __restrict__ A, const float* __restrict__ B,
                  const float* __restrict__ bias, float* __restrict__ C,
                  int M, int N, int K, int doGelu)
{
    __shared__ float As[BKD][BM + 4];
    __shared__ float Bs[BKD][BN + 4];

    int tid = threadIdx.x;
    int tx = tid & 15;      // n micro-tile
    int ty = tid >> 4;      // m micro-tile
    int m0 = blockIdx.y * BM;
    int n0 = blockIdx.x * BN;

    // A: thread loads 8 consecutive floats of one row
    int aRow  = tid >> 1;
    int aKoff = (tid & 1) * 8;
    // B: thread loads 8 consecutive floats of one row
    int bK = tid >> 4;
    int bN = (tid & 15) * 8;

    const float* Aptr = A + (size_t)(m0 + aRow) * K + aKoff;
    const float* Bptr = B + (size_t)bK * N + n0 + bN;

    float4 a0 = *(const float4*)(Aptr);
    float4 a1 = *(const float4*)(Aptr + 4);
    float4 b0 = *(const float4*)(Bptr);
    float4 b1 = *(const float4*)(Bptr + 4);

    float acc[8][8];
    #pragma unroll
    for (int i = 0; i < 8; i++)
        #pragma unroll
        for (int j = 0; j < 8; j++) acc[i][j] = 0.0f;

    for (int k0 = 0; k0 < K; k0 += BKD) {
        // stage regs -> smem (A transposed to [k][m])
        As[aKoff + 0][aRow] = a0.x;
        As[aKoff + 1][aRow] = a0.y;
        As[aKoff + 2][aRow] = a0.z;
        As[aKoff + 3][aRow] = a0.w;
        As[aKoff + 4][aRow] = a1.x;
        As[aKoff + 5][aRow] = a1.y;
        As[aKoff + 6][aRow] = a1.z;
        As[aKoff + 7][aRow] = a1.w;
        *(float4*)&Bs[bK][bN]     = b0;
        *(float4*)&Bs[bK][bN + 4] = b1;
        __syncthreads();

        // prefetch next tile into regs
        if (k0 + BKD < K) {
            const float* An = Aptr + (k0 + BKD);
            a0 = *(const float4*)(An);
            a1 = *(const float4*)(An + 4);
            const float* Bn = Bptr + (size_t)(k0 + BKD) * N;
            b0 = *(const float4*)(Bn);
            b1 = *(const float4*)(Bn + 4);
        }

        // compute
        #pragma unroll
        for (int kk = 0; kk < BKD; kk++) {
            float ar[8], br[8];
            *(float4*)&ar[0] = *(const float4*)&As[kk][ty * 8];
            *(float4*)&ar[4] = *(const float4*)&As[kk][ty * 8 + 4];
            *(float4*)&br[0] = *(const float4*)&Bs[kk][tx * 8];
            *(float4*)&br[4] = *(const float4*)&Bs[kk][tx * 8 + 4];
            #pragma unroll
            for (int i = 0; i < 8; i++)
                #pragma unroll
                for (int j = 0; j < 8; j++)
                    acc[i][j] += ar[i] * br[j];
        }
        __syncthreads();
    }

    // epilogue: + bias (+ gelu)
    float bj[8];
    #pragma unroll
    for (int j = 0; j < 8; j++) bj[j] = bias[n0 + tx * 8 + j];

    #pragma unroll
    for (int i = 0; i < 8; i++) {
        float* crow = C + (size_t)(m0 + ty * 8 + i) * N + n0 + tx * 8;
        #pragma unroll
        for (int j = 0; j < 8; j += 4) {
            float4 rr;
            rr.x = acc[i][j + 0] + bj[j + 0];
            rr.y = acc[i][j + 1] + bj[j + 1];
            rr.z = acc[i][j + 2] + bj[j + 2];
            rr.w = acc[i][j + 3] + bj[j + 3];
            if (doGelu) {
                rr.x = gelu_tanh(rr.x);
                rr.y = gelu_tanh(rr.y);
                rr.z = gelu_tanh(rr.z);
                rr.w = gelu_tanh(rr.w);
            }
            *(float4*)(crow + j) = rr;
        }
    }
}

// ---------------------------------------------------------------------------
// Per-segment attention. One CTA per (b, head) for a given segment.
// smem: Q[len][64] (reused as V), Kt[64][len+1], S[len][len+1]
// ---------------------------------------------------------------------------
__global__ void attn_kernel(const float* __restrict__ q,
                            const float* __restrict__ k,
                            const float* __restrict__ v,
                            float* __restrict__ o,
                            int start, int len)
{
    extern __shared__ float sm[];
    int bid = blockIdx.x;          // 0..2047
    int hh = bid & 7;
    int b  = bid >> 3;
    int tid = threadIdx.x;         // 256
    int h64 = hh * HD;
    size_t rowbase = (size_t)b * LTOT + start;
    int lenp = len + 1;

    float* sQ  = sm;                         // len*64 (later V)
    float* sKt = sm + len * HD;              // 64*(len+1)
    float* sS  = sKt + HD * lenp;            // len*(len+1)

    for (int e = tid; e < len * HD; e += 256) {
        int l = e >> 6, kk = e & 63;
        size_t gi = (rowbase + l) * DM + h64 + kk;
        sQ[e] = q[gi];
        sKt[kk * lenp + l] = k[gi];
    }
    __syncthreads();

    for (int e = tid; e < len * len; e += 256) {
        int l = e / len;
        int m = e - l * len;
        const float* qr = sQ + l * HD;
        const float* kc = sKt + m;
        float acc = 0.0f;
        #pragma unroll 16
        for (int kk = 0; kk < HD; kk++)
            acc += qr[kk] * kc[kk * lenp];
        sS[l * lenp + m] = acc * 0.125f;
    }
    __syncthreads();

    // V load (overwrites Q) + softmax (independent regions)
    for (int e = tid; e < len * HD; e += 256) {
        int l = e >> 6, kk = e & 63;
        sQ[e] = v[(rowbase + l) * DM + h64 + kk];
    }
    if (tid < len) {
        float* row = sS + tid * lenp;
        float mx = -1e30f;
        for (int m = 0; m < len; m++) mx = fmaxf(mx, row[m]);
        float sum = 0.0f;
        for (int m = 0; m < len; m++) {
            float ev = expf(row[m] - mx);
            row[m] = ev;
            sum += ev;
        }
        float inv = 1.0f / sum;
        for (int m = 0; m < len; m++) row[m] *= inv;
    }
    __syncthreads();

    for (int e = tid; e < len * HD; e += 256) {
        int l = e >> 6, d = e & 63;
        const float* srow = sS + l * lenp;
        const float* vc = sQ + d;
        float acc = 0.0f;
        for (int m = 0; m < len; m++)
            acc += srow[m] * vc[m * HD];
        o[(rowbase + l) * DM + h64 + d] = acc;
    }
}

// ---------------------------------------------------------------------------
// Fused residual-add + LayerNorm over D=512. One 128-thread block per row.
// ---------------------------------------------------------------------------
__global__ void ln_kernel(const float* __restrict__ x, const float* __restrict__ res,
                          const float* __restrict__ g, const float* __restrict__ bb,
                          float* __restrict__ out, int hasRes)
{
    int row = blockIdx.x;
    int tid = threadIdx.x;   // 128
    const float4* xr = (const float4*)(x + (size_t)row * DM);
    float4 vv = xr[tid];
    if (hasRes) {
        float4 rr = ((const float4*)(res + (size_t)row * DM))[tid];
        vv.x += rr.x; vv.y += rr.y; vv.z += rr.z; vv.w += rr.w;
    }
    float sum = vv.x + vv.y + vv.z + vv.w;
    float sq  = vv.x * vv.x + vv.y * vv.y + vv.z * vv.z + vv.w * vv.w;

    #pragma unroll
    for (int off = 16; off; off >>= 1) {
        sum += __shfl_xor_sync(0xFFFFFFFFu, sum, off);
        sq  += __shfl_xor_sync(0xFFFFFFFFu, sq,  off);
    }
    __shared__ float red[2][4];
    int w = tid >> 5;
    if ((tid & 31) == 0) { red[0][w] = sum; red[1][w] = sq; }
    __syncthreads();
    sum = red[0][0] + red[0][1] + red[0][2] + red[0][3];
    sq  = red[1][0] + red[1][1] + red[1][2] + red[1][3];

    float mean = sum * (1.0f / DM);
    float var  = sq * (1.0f / DM) - mean * mean;
    float rstd = rsqrtf(var + 1e-5f);

    float4 gv = ((const float4*)g)[tid];
    float4 bv = ((const float4*)bb)[tid];
    float4 ov;
    ov.x = (vv.x - mean) * rstd * gv.x + bv.x;
    ov.y = (vv.y - mean) * rstd * gv.y + bv.y;
    ov.z = (vv.z - mean) * rstd * gv.z + bv.z;
    ov.w = (vv.w - mean) * rstd * gv.w + bv.w;
    ((float4*)(out + (size_t)row * DM))[tid] = ov;
}

// ---------------------------------------------------------------------------
// Host launcher
// ---------------------------------------------------------------------------
extern "C" void kernel_launch(void* const* d_in, const int* in_sizes, int n_in,
                              void* d_out, int out_size)
{
    (void)in_sizes; (void)n_in; (void)out_size;
    const float* x_enc = (const float*)d_in[0];
    const float* W_emb = (const float*)d_in[1];
    const float* Wq    = (const float*)d_in[2];
    const float* bq    = (const float*)d_in[3];
    const float* Wk    = (const float*)d_in[4];
    const float* bk    = (const float*)d_in[5];
    const float* Wv    = (const float*)d_in[6];
    const float* bv    = (const float*)d_in[7];
    const float* Wo    = (const float*)d_in[8];
    const float* bo    = (const float*)d_in[9];
    const float* ln1_g = (const float*)d_in[10];
    const float* ln1_b = (const float*)d_in[11];
    const float* W1    = (const float*)d_in[12];
    const float* b1    = (const float*)d_in[13];
    const float* W2    = (const float*)d_in[14];
    const float* b2    = (const float*)d_in[15];
    const float* ln2_g = (const float*)d_in[16];
    const float* ln2_b = (const float*)d_in[17];
    const float* lnf_g = (const float*)d_in[18];
    const float* lnf_b = (const float*)d_in[19];

    float *h, *qb, *kb, *vb, *tb, *ffb;
    cudaGetSymbolAddress((void**)&h,   g_h);
    cudaGetSymbolAddress((void**)&qb,  g_q);
    cudaGetSymbolAddress((void**)&kb,  g_k);
    cudaGetSymbolAddress((void**)&vb,  g_v);
    cudaGetSymbolAddress((void**)&tb,  g_t);
    cudaGetSymbolAddress((void**)&ffb, g_ff);

    // attention segment 3 needs 131840 B of dynamic smem
    cudaFuncSetAttribute(attn_kernel, cudaFuncAttributeMaxDynamicSharedMemorySize, 135168);

    // ---- embedding ----
    embed_kernel<<<dim3(LTOT, BSEQ), 256>>>(x_enc, W_emb, h);

    const int segStart[4] = {0, 16, 48, 112};
    const int segLen[4]   = {16, 32, 64, 128};

    dim3 gD(DM / BN, MROWS / BM);     // (4, 480)
    dim3 gF(DFF / BN, MROWS / BM);    // (16, 480)

    for (int i = 0; i < NLAYERS; i++) {
        const float* Wq_i = Wq + (size_t)i * DM * DM;
        const float* Wk_i = Wk + (size_t)i * DM * DM;
        const float* Wv_i = Wv + (size_t)i * DM * DM;
        const float* Wo_i = Wo + (size_t)i * DM * DM;
        const float* W1_i = W1 + (size_t)i * DM * DFF;
        const float* W2_i = W2 + (size_t)i * DFF * DM;

        sgemm_kernel<<<gD, 256>>>(h, Wq_i, bq + i * DM, qb, MROWS, DM, DM, 0);
        sgemm_kernel<<<gD, 256>>>(h, Wk_i, bk + i * DM, kb, MROWS, DM, DM, 0);
        sgemm_kernel<<<gD, 256>>>(h, Wv_i, bv + i * DM, vb, MROWS, DM, DM, 0);

        for (int s = 0; s < 4; s++) {
            int len = segLen[s];
            int lenp = len + 1;
            size_t smem = (size_t)(len * HD + HD * lenp + len * lenp) * sizeof(float);
            attn_kernel<<<BSEQ * NHEADS, 256, smem>>>(qb, kb, vb, tb, segStart[s], len);
        }

        sgemm_kernel<<<gD, 256>>>(tb, Wo_i, bo + i * DM, qb, MROWS, DM, DM, 0);
        ln_kernel<<<MROWS, 128>>>(h, qb, ln1_g + i * DM, ln1_b + i * DM, h, 1);

        sgemm_kernel<<<gF, 256>>>(h, W1_i, b1 + i * DFF, ffb, MROWS, DFF, DM, 1);
        sgemm_kernel<<<gD, 256>>>(ffb, W2_i, b2 + i * DM, qb, MROWS, DM, DFF, 0);
        ln_kernel<<<MROWS, 128>>>(h, qb, ln2_g + i * DM, ln2_b + i * DM, h, 1);
    }

    // ---- final LN -> output ----
    ln_kernel<<<MROWS, 128>>>(h, nullptr, lnf_g, lnf_b, (float*)d_out, 0);
}

// round 7
// speedup vs baseline: 3.4358x; 3.4358x over previous
#include <cuda_runtime.h>
#include <cuda_bf16.h>
#include <cstdint>

#define BS       8
#define CCH      32
#define TLEN     2048
#define PATCH_N  16
#define DM       512
#define NHEADS   8
#define HD       64
#define DFF      2048
#define NLAYERS  3
#define BSEQ     (BS * CCH)       // 256
#define LTOT     240
#define MROWS    (BSEQ * LTOT)    // 61440

// ---------------- scratch ----------------
__device__ float g_h [MROWS * DM];
__device__ float g_q [MROWS * DM];
__device__ float g_k [MROWS * DM];
__device__ float g_v [MROWS * DM];
__device__ float g_t [MROWS * DM];
__device__ float g_ff[(size_t)MROWS * DFF];

// ---------------- helpers ----------------
__device__ __forceinline__ uint32_t smem_u32(const void* p) {
    uint32_t a;
    asm("{ .reg .u64 t; cvta.to.shared.u64 t, %1; cvt.u32.u64 %0, t; }"
        : "=r"(a) : "l"(p));
    return a;
}

__device__ __forceinline__ float gelu_tanh(float x) {
    float x3 = x * x * x;
    float t = tanhf(0.7978845608028654f * (x + 0.044715f * x3));
    return 0.5f * x * (1.0f + t);
}

#define LDSM_X4(r0, r1, r2, r3, addr) \
    asm volatile("ldmatrix.sync.aligned.m8n8.x4.shared.b16 {%0,%1,%2,%3}, [%4];" \
                 : "=r"(r0), "=r"(r1), "=r"(r2), "=r"(r3) : "r"(addr))

#define LDSM_X4_T(r0, r1, r2, r3, addr) \
    asm volatile("ldmatrix.sync.aligned.m8n8.x4.trans.shared.b16 {%0,%1,%2,%3}, [%4];" \
                 : "=r"(r0), "=r"(r1), "=r"(r2), "=r"(r3) : "r"(addr))

#define MMA_BF16(d, a, b0v, b1v) \
    asm volatile("mma.sync.aligned.m16n8k16.row.col.f32.bf16.bf16.f32 " \
                 "{%0,%1,%2,%3}, {%4,%5,%6,%7}, {%8,%9}, {%0,%1,%2,%3};" \
                 : "+f"((d)[0]), "+f"((d)[1]), "+f"((d)[2]), "+f"((d)[3]) \
                 : "r"((a)[0]), "r"((a)[1]), "r"((a)[2]), "r"((a)[3]), \
                   "r"(b0v), "r"(b1v))

__device__ __forceinline__ uint32_t pack2bf(float x, float y) {
    __nv_bfloat162 h = __floats2bfloat162_rn(x, y);
    return *reinterpret_cast<uint32_t*>(&h);
}
__device__ __forceinline__ float bfhi(float x) {
    return __bfloat162float(__float2bfloat16(x));
}

// ---------------- embedding ----------------
__global__ void embed_kernel(const float* __restrict__ x_enc,
                             const float* __restrict__ Wemb,
                             float* __restrict__ h)
{
    int tok = blockIdx.x;
    int r   = blockIdx.y;
    int tid = threadIdx.x;
    int b  = r >> 5;
    int cc = r & 31;

    int kstr, j;
    if (tok < 16)       { kstr = 8; j = tok; }
    else if (tok < 48)  { kstr = 4; j = tok - 16; }
    else if (tok < 112) { kstr = 2; j = tok - 48; }
    else                { kstr = 1; j = tok - 112; }

    __shared__ float xv[PATCH_N];
    if (tid < PATCH_N) {
        int tt = kstr * (j * PATCH_N + tid);
        xv[tid] = x_enc[((size_t)b * TLEN + tt) * CCH + cc];
    }
    __syncthreads();

    float pepos = (float)(j * kstr);
    const float cln = 9.210340371976184f / (float)DM;

    for (int d = tid; d < DM; d += 256) {
        float acc = 0.0f;
        #pragma unroll
        for (int p = 0; p < PATCH_N; p++)
            acc += xv[p] * Wemb[p * DM + d];
        int i2 = d & ~1;
        float ang = pepos * __expf(-(float)i2 * cln);
        float pv = (d & 1) ? cosf(ang) : sinf(ang);
        h[((size_t)r * LTOT + tok) * DM + d] = acc + pv;
    }
}

// ---------------- mma.sync bf16x3 GEMM ----------------
// C[M,N] = A[M,K] @ B[K,N] + bias (+gelu). CTA tile 128x128, K-slab 32.
// 8 warps: wm = wid&3 (32 rows each), wn = wid>>2 (64 cols each).
#define A_STRIDE 40    // elements per A smem row (32 + 8 pad) -> 80B, ldsm conflict-free
#define B_STRIDE 136   // elements per B smem row (128 + 8 pad) -> 272B, conflict-free

__global__ __launch_bounds__(256, 1)
void gemm_mma(const float* __restrict__ A, const float* __restrict__ Bm,
              const float* __restrict__ bias, float* __restrict__ C,
              int M, int N, int K, int doGelu)
{
    __shared__ __align__(16) uint16_t sAh[128 * A_STRIDE];
    __shared__ __align__(16) uint16_t sAl[128 * A_STRIDE];
    __shared__ __align__(16) uint16_t sBh[32 * B_STRIDE];
    __shared__ __align__(16) uint16_t sBl[32 * B_STRIDE];

    int tid  = threadIdx.x;
    int wid  = tid >> 5;
    int lane = tid & 31;
    int wm = wid & 3;
    int wn = wid >> 2;
    int m0 = blockIdx.y * 128;
    int n0 = blockIdx.x * 128;

    float acc[2][8][4];
    #pragma unroll
    for (int i = 0; i < 2; i++)
        #pragma unroll
        for (int j = 0; j < 8; j++)
            #pragma unroll
            for (int c = 0; c < 4; c++) acc[i][j][c] = 0.0f;

    // ldmatrix base addresses (byte, shared state space)
    uint32_t aBaseH = smem_u32(sAh);
    uint32_t aBaseL = smem_u32(sAl);
    uint32_t bBaseH = smem_u32(sBh);
    uint32_t bBaseL = smem_u32(sBl);

    // per-lane ldmatrix offsets
    // A frag (m16k16): rows wm*32 + mf*16 + (lane&15), col (lane>>4)*8
    uint32_t aoff0 = ((uint32_t)((wm * 32 + (lane & 15)) * A_STRIDE + (lane >> 4) * 8)) * 2;
    // B frag (k16n16 block): row (lane&7) + ((lane>>3)&1)*8, col wn*64 + nb*16 + (lane>>4)*8
    uint32_t boff0 = ((uint32_t)(((lane & 7) + ((lane >> 3) & 1) * 8) * B_STRIDE
                                 + wn * 64 + (lane >> 4) * 8)) * 2;

    int nslab = K >> 5;

    float4 aReg[4];
    float4 bReg[4];

    auto prefetch = [&](int j) {
        int k0 = j * 32;
        #pragma unroll
        for (int i = 0; i < 4; i++) {
            int idx = i * 256 + tid;
            int row = idx >> 3, c4 = idx & 7;
            aReg[i] = *(const float4*)(A + (size_t)(m0 + row) * K + k0 + c4 * 4);
        }
        #pragma unroll
        for (int i = 0; i < 4; i++) {
            int idx = i * 256 + tid;
            int row = idx >> 5, c4 = idx & 31;
            bReg[i] = *(const float4*)(Bm + (size_t)(k0 + row) * N + n0 + c4 * 4);
        }
    };

    auto stage = [&]() {
        #pragma unroll
        for (int i = 0; i < 4; i++) {
            int idx = i * 256 + tid;
            int row = idx >> 3, c4 = idx & 7;
            float4 v = aReg[i];
            float hx = bfhi(v.x), hy = bfhi(v.y), hz = bfhi(v.z), hw = bfhi(v.w);
            uint2 hi = make_uint2(pack2bf(hx, hy), pack2bf(hz, hw));
            uint2 lo = make_uint2(pack2bf(v.x - hx, v.y - hy), pack2bf(v.z - hz, v.w - hw));
            int e = row * A_STRIDE + c4 * 4;
            *(uint2*)(sAh + e) = hi;
            *(uint2*)(sAl + e) = lo;
        }
        #pragma unroll
        for (int i = 0; i < 4; i++) {
            int idx = i * 256 + tid;
            int row = idx >> 5, c4 = idx & 31;
            float4 v = bReg[i];
            float hx = bfhi(v.x), hy = bfhi(v.y), hz = bfhi(v.z), hw = bfhi(v.w);
            uint2 hi = make_uint2(pack2bf(hx, hy), pack2bf(hz, hw));
            uint2 lo = make_uint2(pack2bf(v.x - hx, v.y - hy), pack2bf(v.z - hz, v.w - hw));
            int e = row * B_STRIDE + c4 * 4;
            *(uint2*)(sBh + e) = hi;
            *(uint2*)(sBl + e) = lo;
        }
    };

    prefetch(0);
    for (int j = 0; j < nslab; j++) {
        stage();
        __syncthreads();
        if (j + 1 < nslab) prefetch(j + 1);

        #pragma unroll
        for (int ks = 0; ks < 2; ks++) {
            uint32_t kbyteA = (uint32_t)(ks * 16) * 2;
            uint32_t kbyteB = (uint32_t)(ks * 16 * B_STRIDE) * 2;

            uint32_t ah[2][4], al[2][4];
            #pragma unroll
            for (int mf = 0; mf < 2; mf++) {
                uint32_t off = aoff0 + (uint32_t)(mf * 16 * A_STRIDE) * 2 + kbyteA;
                LDSM_X4(ah[mf][0], ah[mf][1], ah[mf][2], ah[mf][3], aBaseH + off);
                LDSM_X4(al[mf][0], al[mf][1], al[mf][2], al[mf][3], aBaseL + off);
            }
            uint32_t bh[16], bl[16];
            #pragma unroll
            for (int nb = 0; nb < 4; nb++) {
                uint32_t off = boff0 + (uint32_t)(nb * 16) * 2 + kbyteB;
                LDSM_X4_T(bh[nb * 4 + 0], bh[nb * 4 + 1], bh[nb * 4 + 2], bh[nb * 4 + 3], bBaseH + off);
                LDSM_X4_T(bl[nb * 4 + 0], bl[nb * 4 + 1], bl[nb * 4 + 2], bl[nb * 4 + 3], bBaseL + off);
            }

            #pragma unroll
            for (int mf = 0; mf < 2; mf++)
                #pragma unroll
                for (int nf = 0; nf < 8; nf++) {
                    MMA_BF16(acc[mf][nf], ah[mf], bh[nf * 2], bh[nf * 2 + 1]);
                    MMA_BF16(acc[mf][nf], ah[mf], bl[nf * 2], bl[nf * 2 + 1]);
                    MMA_BF16(acc[mf][nf], al[mf], bh[nf * 2], bh[nf * 2 + 1]);
                }
        }
        __syncthreads();
    }

    // epilogue: accum frag (mf,nf): d0=(r,c) d1=(r,c+1) d2=(r+8,c) d3=(r+8,c+1)
    int rbase = m0 + wm * 32 + (lane >> 2);
    int cbase = n0 + wn * 64 + (lane & 3) * 2;
    #pragma unroll
    for (int mf = 0; mf < 2; mf++) {
        #pragma unroll
        for (int nf = 0; nf < 8; nf++) {
            int col = cbase + nf * 8;
            float b0v = bias[col], b1v = bias[col + 1];
            float v0 = acc[mf][nf][0] + b0v;
            float v1 = acc[mf][nf][1] + b1v;
            float v2 = acc[mf][nf][2] + b0v;
            float v3 = acc[mf][nf][3] + b1v;
            if (doGelu) {
                v0 = gelu_tanh(v0); v1 = gelu_tanh(v1);
                v2 = gelu_tanh(v2); v3 = gelu_tanh(v3);
            }
            int r0 = rbase + mf * 16;
            float2 p0 = make_float2(v0, v1);
            float2 p1 = make_float2(v2, v3);
            *(float2*)(C + (size_t)r0 * N + col) = p0;
            *(float2*)(C + (size_t)(r0 + 8) * N + col) = p1;
        }
    }
}

// ---------------- per-segment attention (float4-tiled) ----------------
__global__ void attn_kernel(const float* __restrict__ q,
                            const float* __restrict__ k,
                            const float* __restrict__ v,
                            float* __restrict__ o,
                            int start, int len)
{
    extern __shared__ float sm[];
    int bid = blockIdx.x;
    int hh = bid & 7;
    int b  = bid >> 3;
    int tid = threadIdx.x;        // 256
    int h64 = hh * HD;
    size_t rowbase = (size_t)b * LTOT + start;
    int lenp = len + 4;

    float* sQ  = sm;                       // len*64  (later V)
    float* sKt = sm + len * HD;            // 64*(len+4)
    float* sS  = sKt + HD * lenp;          // len*(len+4)

    for (int e = tid; e < len * HD; e += 256) {
        int l = e >> 6, kk = e & 63;
        size_t gi = (rowbase + l) * DM + h64 + kk;
        sQ[e] = q[gi];
        sKt[kk * lenp + l] = k[gi];
    }
    __syncthreads();

    int nq4 = len >> 2;
    for (int e = tid; e < len * nq4; e += 256) {
        int l  = e / nq4;
        int m4 = (e - l * nq4) * 4;
        const float* qr = sQ + l * HD;
        float ax = 0.0f, ay = 0.0f, az = 0.0f, aw = 0.0f;
        #pragma unroll 8
        for (int kk = 0; kk < HD; kk++) {
            float qv = qr[kk];
            float4 kv = *(const float4*)&sKt[kk * lenp + m4];
            ax += qv * kv.x; ay += qv * kv.y;
            az += qv * kv.z; aw += qv * kv.w;
        }
        float4 rr; rr.x = ax * 0.125f; rr.y = ay * 0.125f;
        rr.z = az * 0.125f; rr.w = aw * 0.125f;
        *(float4*)&sS[l * lenp + m4] = rr;
    }
    __syncthreads();

    for (int e = tid; e < len * HD; e += 256) {
        int l = e >> 6, kk = e & 63;
        sQ[e] = v[(rowbase + l) * DM + h64 + kk];
    }
    if (tid < len) {
        float* row = sS + tid * lenp;
        float mx = -1e30f;
        for (int m = 0; m < len; m++) mx = fmaxf(mx, row[m]);
        float sum = 0.0f;
        for (int m = 0; m < len; m++) {
            float ev = expf(row[m] - mx);
            row[m] = ev;
            sum += ev;
        }
        float inv = 1.0f / sum;
        for (int m = 0; m < len; m++) row[m] *= inv;
    }
    __syncthreads();

    for (int e = tid; e < len * (HD / 4); e += 256) {
        int l  = e >> 4;
        int d4 = (e & 15) * 4;
        const float* srow = sS + l * lenp;
        float ax = 0.0f, ay = 0.0f, az = 0.0f, aw = 0.0f;
        #pragma unroll 8
        for (int m = 0; m < len; m++) {
            float s = srow[m];
            float4 vv = *(const float4*)&sQ[m * HD + d4];
            ax += s * vv.x; ay += s * vv.y;
            az += s * vv.z; aw += s * vv.w;
        }
        float4 rr; rr.x = ax; rr.y = ay; rr.z = az; rr.w = aw;
        *(float4*)&o[(rowbase + l) * DM + h64 + d4] = rr;
    }
}

// ---------------- residual + LayerNorm ----------------
__global__ void ln_kernel(const float* __restrict__ x, const float* __restrict__ res,
                          const float* __restrict__ g, const float* __restrict__ bb,
                          float* __restrict__ out, int hasRes)
{
    int row = blockIdx.x;
    int tid = threadIdx.x;   // 128
    float4 vv = ((const float4*)(x + (size_t)row * DM))[tid];
    if (hasRes) {
        float4 rr = ((const float4*)(res + (size_t)row * DM))[tid];
        vv.x += rr.x; vv.y += rr.y; vv.z += rr.z; vv.w += rr.w;
    }
    float sum = vv.x + vv.y + vv.z + vv.w;
    float sq  = vv.x * vv.x + vv.y * vv.y + vv.z * vv.z + vv.w * vv.w;

    #pragma unroll
    for (int off = 16; off; off >>= 1) {
        sum += __shfl_xor_sync(0xFFFFFFFFu, sum, off);
        sq  += __shfl_xor_sync(0xFFFFFFFFu, sq,  off);
    }
    __shared__ float red[2][4];
    int w = tid >> 5;
    if ((tid & 31) == 0) { red[0][w] = sum; red[1][w] = sq; }
    __syncthreads();
    sum = red[0][0] + red[0][1] + red[0][2] + red[0][3];
    sq  = red[1][0] + red[1][1] + red[1][2] + red[1][3];

    float mean = sum * (1.0f / DM);
    float var  = sq * (1.0f / DM) - mean * mean;
    float rstd = rsqrtf(var + 1e-5f);

    float4 gv = ((const float4*)g)[tid];
    float4 bv = ((const float4*)bb)[tid];
    float4 ov;
    ov.x = (vv.x - mean) * rstd * gv.x + bv.x;
    ov.y = (vv.y - mean) * rstd * gv.y + bv.y;
    ov.z = (vv.z - mean) * rstd * gv.z + bv.z;
    ov.w = (vv.w - mean) * rstd * gv.w + bv.w;
    ((float4*)(out + (size_t)row * DM))[tid] = ov;
}

// ---------------- host launcher ----------------
extern "C" void kernel_launch(void* const* d_in, const int* in_sizes, int n_in,
                              void* d_out, int out_size)
{
    (void)in_sizes; (void)n_in; (void)out_size;
    const float* x_enc = (const float*)d_in[0];
    const float* W_emb = (const float*)d_in[1];
    const float* Wq    = (const float*)d_in[2];
    const float* bq    = (const float*)d_in[3];
    const float* Wk    = (const float*)d_in[4];
    const float* bk    = (const float*)d_in[5];
    const float* Wv    = (const float*)d_in[6];
    const float* bv    = (const float*)d_in[7];
    const float* Wo    = (const float*)d_in[8];
    const float* bo    = (const float*)d_in[9];
    const float* ln1_g = (const float*)d_in[10];
    const float* ln1_b = (const float*)d_in[11];
    const float* W1    = (const float*)d_in[12];
    const float* b1    = (const float*)d_in[13];
    const float* W2    = (const float*)d_in[14];
    const float* b2    = (const float*)d_in[15];
    const float* ln2_g = (const float*)d_in[16];
    const float* ln2_b = (const float*)d_in[17];
    const float* lnf_g = (const float*)d_in[18];
    const float* lnf_b = (const float*)d_in[19];

    float *h, *qb, *kb, *vb, *tb, *ffb;
    cudaGetSymbolAddress((void**)&h,   g_h);
    cudaGetSymbolAddress((void**)&qb,  g_q);
    cudaGetSymbolAddress((void**)&kb,  g_k);
    cudaGetSymbolAddress((void**)&vb,  g_v);
    cudaGetSymbolAddress((void**)&tb,  g_t);
    cudaGetSymbolAddress((void**)&ffb, g_ff);

    cudaFuncSetAttribute(attn_kernel, cudaFuncAttributeMaxDynamicSharedMemorySize, 140000);

    embed_kernel<<<dim3(LTOT, BSEQ), 256>>>(x_enc, W_emb, h);

    const int segStart[4] = {0, 16, 48, 112};
    const int segLen[4]   = {16, 32, 64, 128};

    dim3 gD(DM / 128, MROWS / 128);    // (4, 480)
    dim3 gF(DFF / 128, MROWS / 128);   // (16, 480)

    for (int i = 0; i < NLAYERS; i++) {
        const float* Wq_i = Wq + (size_t)i * DM * DM;
        const float* Wk_i = Wk + (size_t)i * DM * DM;
        const float* Wv_i = Wv + (size_t)i * DM * DM;
        const float* Wo_i = Wo + (size_t)i * DM * DM;
        const float* W1_i = W1 + (size_t)i * DM * DFF;
        const float* W2_i = W2 + (size_t)i * DFF * DM;

        gemm_mma<<<gD, 256>>>(h, Wq_i, bq + i * DM, qb, MROWS, DM, DM, 0);
        gemm_mma<<<gD, 256>>>(h, Wk_i, bk + i * DM, kb, MROWS, DM, DM, 0);
        gemm_mma<<<gD, 256>>>(h, Wv_i, bv + i * DM, vb, MROWS, DM, DM, 0);

        for (int s = 0; s < 4; s++) {
            int len = segLen[s];
            int lenp = len + 4;
            size_t smem = (size_t)(len * HD + HD * lenp + len * lenp) * sizeof(float);
            attn_kernel<<<BSEQ * NHEADS, 256, smem>>>(qb, kb, vb, tb, segStart[s], len);
        }

        gemm_mma<<<gD, 256>>>(tb, Wo_i, bo + i * DM, qb, MROWS, DM, DM, 0);
        ln_kernel<<<MROWS, 128>>>(h, qb, ln1_g + i * DM, ln1_b + i * DM, h, 1);

        gemm_mma<<<gF, 256>>>(h, W1_i, b1 + i * DFF, ffb, MROWS, DFF, DM, 1);
        gemm_mma<<<gD, 256>>>(ffb, W2_i, b2 + i * DM, qb, MROWS, DM, DFF, 0);
        ln_kernel<<<MROWS, 128>>>(h, qb, ln2_g + i * DM, ln2_b + i * DM, h, 1);
    }

    ln_kernel<<<MROWS, 128>>>(h, nullptr, lnf_g, lnf_b, (float*)d_out, 0);
}